// round 4
// baseline (speedup 1.0000x reference)
#include <cuda_runtime.h>
#include <math.h>

// Problem constants
#define NROWS 65536
#define PDIM  512
#define HDIM  256
#define DIN   768     // P + HD
#define D1    200
#define D2    100
#define D3    100
#define DOUT  512

#define ROWS  32      // rows per block
#define TH    256     // threads per block

// Shared memory layout (floats)
#define XS_OFF   0
#define XS_F     (ROWS*DIN)            // 24576
#define H1_OFF   (XS_OFF + XS_F)       // 24576
#define H1_F     (ROWS*D1)             // 6400
#define H2_OFF   (H1_OFF + H1_F)       // 30976
#define H2_F     (ROWS*D2)             // 3200
#define H3_OFF   (H2_OFF + H2_F)       // 34176
#define H3_F     (ROWS*D3)             // 3200
#define WS_OFF   (H3_OFF + H3_F)       // 37376
#define WS_F     7200                  // max(200*36, 100*36, 512*12)
#define SMEM_F   (WS_OFF + WS_F)       // 44576
#define SMEM_BYTES (SMEM_F * 4)        // 178304

// Global accumulators (graph-replayed, zeroed each launch by zero_kernel)
__device__ double g_mu[HDIM];
__device__ double g_S;
__device__ double g_diff;
__device__ double g_part0;

__global__ void zero_kernel() {
    int t = threadIdx.x;
    if (t < HDIM) g_mu[t] = 0.0;
    if (t == 0) { g_S = 0.0; g_diff = 0.0; g_part0 = 0.0; }
}

__global__ __launch_bounds__(TH, 1)
void mlp_kernel(const float* __restrict__ input,
                const float* __restrict__ h,
                const float* __restrict__ W1,  const float* __restrict__ b1,
                const float* __restrict__ W12, const float* __restrict__ b12,
                const float* __restrict__ W13, const float* __restrict__ b13,
                const float* __restrict__ W2,  const float* __restrict__ b2,
                float* __restrict__ out)
{
    extern __shared__ float smem[];
    float* xS  = smem + XS_OFF;
    float* h1S = smem + H1_OFF;
    float* h2S = smem + H2_OFF;
    float* h3S = smem + H3_OFF;
    float* wS  = smem + WS_OFF;

    const int tid = threadIdx.x;
    const int tx  = tid & 31;
    const int ty  = tid >> 5;          // warp id 0..7
    const int row0 = blockIdx.x * ROWS;

    // ---- Load x tile = [input | h] as float4, coalesced ----
    {
        const float4* in4 = (const float4*)input;
        const float4* h4  = (const float4*)h;
        float4* x4 = (float4*)xS;
        #pragma unroll 4
        for (int i = tid; i < ROWS * (DIN/4); i += TH) {
            int r  = i / (DIN/4);
            int k4 = i % (DIN/4);
            float4 v;
            if (k4 < PDIM/4) v = in4[(size_t)(row0 + r) * (PDIM/4) + k4];
            else             v = h4 [(size_t)(row0 + r) * (HDIM/4) + (k4 - PDIM/4)];
            x4[r * (DIN/4) + k4] = v;
        }
    }
    __syncthreads();

    // ================= Layer 1: (32x768) @ W1^T -> relu (32x200) =============
    {
        float acc[4][7];
        #pragma unroll
        for (int i = 0; i < 4; i++)
            #pragma unroll
            for (int j = 0; j < 7; j++) {
                int c = tx + 32*j;
                acc[i][j] = (c < D1) ? b1[c] : 0.f;
            }
        for (int k0 = 0; k0 < DIN; k0 += 32) {
            __syncthreads();
            // stage W1 chunk: wS[c*36 + kl] = W1[c*768 + k0 + kl]
            for (int i = tid; i < D1*32; i += TH) {
                int c = i >> 5, kl = i & 31;
                wS[c*36 + kl] = W1[c*DIN + k0 + kl];
            }
            __syncthreads();
            #pragma unroll
            for (int kk = 0; kk < 32; kk += 4) {
                float4 xq[4];
                #pragma unroll
                for (int i = 0; i < 4; i++)
                    xq[i] = *(const float4*)&xS[(ty*4+i)*DIN + k0 + kk];
                #pragma unroll
                for (int j = 0; j < 7; j++) {
                    int c = tx + 32*j;
                    if (c < D1) {
                        float4 w = *(const float4*)&wS[c*36 + kk];
                        #pragma unroll
                        for (int i = 0; i < 4; i++)
                            acc[i][j] += xq[i].x*w.x + xq[i].y*w.y + xq[i].z*w.z + xq[i].w*w.w;
                    }
                }
            }
        }
        #pragma unroll
        for (int i = 0; i < 4; i++)
            #pragma unroll
            for (int j = 0; j < 7; j++) {
                int c = tx + 32*j;
                if (c < D1) h1S[(ty*4+i)*D1 + c] = fmaxf(acc[i][j], 0.f);
            }
    }

    // ================= Layer 2: (32x200) @ W12^T -> relu (32x100) ============
    {
        float acc[4][4];
        #pragma unroll
        for (int i = 0; i < 4; i++)
            #pragma unroll
            for (int j = 0; j < 4; j++) {
                int c = tx + 32*j;
                acc[i][j] = (c < D2) ? b12[c] : 0.f;
            }
        for (int k0 = 0; k0 < D1; k0 += 32) {
            int kc = min(32, D1 - k0);
            __syncthreads();
            for (int i = tid; i < D2*kc; i += TH) {
                int c = i / kc, kl = i % kc;
                wS[c*36 + kl] = W12[c*D1 + k0 + kl];
            }
            __syncthreads();
            for (int kk = 0; kk < kc; kk += 4) {
                float4 xq[4];
                #pragma unroll
                for (int i = 0; i < 4; i++)
                    xq[i] = *(const float4*)&h1S[(ty*4+i)*D1 + k0 + kk];
                #pragma unroll
                for (int j = 0; j < 4; j++) {
                    int c = tx + 32*j;
                    if (c < D2) {
                        float4 w = *(const float4*)&wS[c*36 + kk];
                        #pragma unroll
                        for (int i = 0; i < 4; i++)
                            acc[i][j] += xq[i].x*w.x + xq[i].y*w.y + xq[i].z*w.z + xq[i].w*w.w;
                    }
                }
            }
        }
        __syncthreads();
        #pragma unroll
        for (int i = 0; i < 4; i++)
            #pragma unroll
            for (int j = 0; j < 4; j++) {
                int c = tx + 32*j;
                if (c < D2) h2S[(ty*4+i)*D2 + c] = fmaxf(acc[i][j], 0.f);
            }
    }

    // ================= Layer 3: (32x100) @ W13^T -> relu (32x100) ============
    {
        float acc[4][4];
        #pragma unroll
        for (int i = 0; i < 4; i++)
            #pragma unroll
            for (int j = 0; j < 4; j++) {
                int c = tx + 32*j;
                acc[i][j] = (c < D3) ? b13[c] : 0.f;
            }
        for (int k0 = 0; k0 < D2; k0 += 32) {
            int kc = min(32, D2 - k0);
            __syncthreads();
            for (int i = tid; i < D3*kc; i += TH) {
                int c = i / kc, kl = i % kc;
                wS[c*36 + kl] = W13[c*D2 + k0 + kl];
            }
            __syncthreads();
            for (int kk = 0; kk < kc; kk += 4) {
                float4 xq[4];
                #pragma unroll
                for (int i = 0; i < 4; i++)
                    xq[i] = *(const float4*)&h2S[(ty*4+i)*D2 + k0 + kk];
                #pragma unroll
                for (int j = 0; j < 4; j++) {
                    int c = tx + 32*j;
                    if (c < D3) {
                        float4 w = *(const float4*)&wS[c*36 + kk];
                        #pragma unroll
                        for (int i = 0; i < 4; i++)
                            acc[i][j] += xq[i].x*w.x + xq[i].y*w.y + xq[i].z*w.z + xq[i].w*w.w;
                    }
                }
            }
        }
        __syncthreads();
        #pragma unroll
        for (int i = 0; i < 4; i++)
            #pragma unroll
            for (int j = 0; j < 4; j++) {
                int c = tx + 32*j;
                if (c < D3) h3S[(ty*4+i)*D3 + c] = fmaxf(acc[i][j], 0.f);
            }
    }

    // ================= Layer 4: (32x100) @ W2^T + b2 -> (32x512) =============
    {
        float acc[4][16];
        #pragma unroll
        for (int i = 0; i < 4; i++)
            #pragma unroll
            for (int j = 0; j < 16; j++)
                acc[i][j] = b2[tx + 32*j];
        for (int k0 = 0; k0 < D3; k0 += 12) {
            int kc = min(12, D3 - k0);
            __syncthreads();
            for (int i = tid; i < DOUT*kc; i += TH) {
                int c = i / kc, kl = i % kc;
                wS[c*12 + kl] = W2[c*D3 + k0 + kl];
            }
            __syncthreads();
            for (int kk = 0; kk < kc; kk += 4) {
                float4 xq[4];
                #pragma unroll
                for (int i = 0; i < 4; i++)
                    xq[i] = *(const float4*)&h3S[(ty*4+i)*D3 + k0 + kk];
                #pragma unroll
                for (int j = 0; j < 16; j++) {
                    int c = tx + 32*j;
                    float4 w = *(const float4*)&wS[c*12 + kk];
                    #pragma unroll
                    for (int i = 0; i < 4; i++)
                        acc[i][j] += xq[i].x*w.x + xq[i].y*w.y + xq[i].z*w.z + xq[i].w*w.w;
                }
            }
        }

        // Epilogue: store f_x_h + fused part0 accumulation
        float dd = 0.f;
        #pragma unroll
        for (int i = 0; i < 4; i++) {
            int r  = ty*4 + i;
            int rg = row0 + r;
            #pragma unroll
            for (int j = 0; j < 16; j++) {
                int c = tx + 32*j;
                float o = acc[i][j];
                out[(size_t)rg * PDIM + c] = o;
                if (rg < NROWS - 1) {
                    float nx = (r < ROWS - 1) ? xS[(r+1)*DIN + c]
                                              : input[(size_t)(rg+1) * PDIM + c];
                    float d = o - nx;
                    dd += d * d;
                }
            }
        }
        // warp reduce dd
        #pragma unroll
        for (int off = 16; off > 0; off >>= 1)
            dd += __shfl_down_sync(0xFFFFFFFFu, dd, off);
        __shared__ float warp_dd[8];
        if (tx == 0) warp_dd[ty] = dd;
        __syncthreads();
        if (tid == 0) {
            float s = 0.f;
            #pragma unroll
            for (int w = 0; w < 8; w++) s += warp_dd[w];
            atomicAdd(&g_part0, (double)s);
        }
    }
}

// h statistics: column sums (mu), sum of squares (S), total variation (diff)
__global__ __launch_bounds__(HDIM)
void hred_kernel(const float* __restrict__ h)
{
    const int c  = threadIdx.x;      // column 0..255
    const int r0 = blockIdx.x * 256; // 256 rows per block
    float prev = (r0 > 0) ? h[(size_t)(r0-1)*HDIM + c] : 0.f;
    float cs = 0.f, sq = 0.f, df = 0.f;
    #pragma unroll 4
    for (int i = 0; i < 256; i++) {
        float v = h[(size_t)(r0 + i)*HDIM + c];
        cs += v;
        sq += v * v;
        if (r0 + i > 0) df += fabsf(v - prev);
        prev = v;
    }
    atomicAdd(&g_mu[c], (double)cs);

    // block reduce sq, df
    #pragma unroll
    for (int off = 16; off > 0; off >>= 1) {
        sq += __shfl_down_sync(0xFFFFFFFFu, sq, off);
        df += __shfl_down_sync(0xFFFFFFFFu, df, off);
    }
    __shared__ float wsq[8], wdf[8];
    int tx = c & 31, ty = c >> 5;
    if (tx == 0) { wsq[ty] = sq; wdf[ty] = df; }
    __syncthreads();
    if (c == 0) {
        float s1 = 0.f, s2 = 0.f;
        #pragma unroll
        for (int w = 0; w < 8; w++) { s1 += wsq[w]; s2 += wdf[w]; }
        atomicAdd(&g_S, (double)s1);
        atomicAdd(&g_diff, (double)s2);
    }
}

__global__ void finalize_kernel(float* __restrict__ out, long long base)
{
    __shared__ double red[HDIM];
    int t = threadIdx.x;
    red[t] = fabs(g_mu[t]);
    __syncthreads();
    for (int s = 128; s > 0; s >>= 1) {
        if (t < s) red[t] += red[t + s];
        __syncthreads();
    }
    if (t == 0) {
        const double Nn = (double)NROWS;
        out[base + 0] = (float)(sqrt(g_part0) / (Nn - 1.0));           // part0
        out[base + 1] = (float)(red[0] / Nn / (double)HDIM);           // part1
        out[base + 2] = (float)fabs(g_S / Nn / (double)HDIM - 1.0);    // part2
        out[base + 3] = (float)(g_diff / (Nn - 1.0) / (double)HDIM);   // part3
    }
}

extern "C" void kernel_launch(void* const* d_in, const int* in_sizes, int n_in,
                              void* d_out, int out_size)
{
    const float* input = (const float*)d_in[0];
    const float* h     = (const float*)d_in[1];
    const float* W1    = (const float*)d_in[2];
    const float* b1    = (const float*)d_in[3];
    const float* W12   = (const float*)d_in[4];
    const float* b12   = (const float*)d_in[5];
    const float* W13   = (const float*)d_in[6];
    const float* b13   = (const float*)d_in[7];
    const float* W2    = (const float*)d_in[8];
    const float* b2    = (const float*)d_in[9];
    float* out = (float*)d_out;

    cudaFuncSetAttribute(mlp_kernel, cudaFuncAttributeMaxDynamicSharedMemorySize, SMEM_BYTES);

    zero_kernel<<<1, 256>>>();
    mlp_kernel<<<NROWS / ROWS, TH, SMEM_BYTES>>>(input, h, W1, b1, W12, b12,
                                                 W13, b13, W2, b2, out);
    hred_kernel<<<NROWS / 256, HDIM>>>(h);
    finalize_kernel<<<1, HDIM>>>(out, (long long)out_size - 4);
}

// round 6
// speedup vs baseline: 2.2346x; 2.2346x over previous
#include <cuda_runtime.h>
#include <math.h>

// Problem constants
#define NROWS 65536
#define PDIM  512
#define HDIM  256
#define DIN   768
#define D1    200
#define D2    100
#define D3    100
#define DOUT  512

#define ROWS  64      // rows per block
#define TH    256     // threads per block (8 warps)

// Shared memory layout (floats).  h2S aliases xS (x dead before h2 written).
// Strides chosen so stride mod 32 ∈ {4,12,20} -> conflict-free fragment LDS.
#define H2_OFF   0                      // 64 x 108  (also xS: 64 x 68)
#define H2_SZ    (64*108)               // 6912
#define H3_OFF   (H2_OFF + H2_SZ)       // 6912 : 64 x 108
#define H3_SZ    (64*108)
#define H1_OFF   (H3_OFF + H3_SZ)       // 13824 : 64 x 212
#define H1_SZ    (64*212)
#define WS_OFF   (H1_OFF + H1_SZ)       // 27392
#define WS_SZ    (104*204)              // 21216 (max of all weight stagings)
#define SMEM_F   (WS_OFF + WS_SZ)       // 48608 floats
#define SMEM_BYTES (SMEM_F * 4)         // 194432 bytes

// Global accumulators
__device__ double g_mu[HDIM];
__device__ double g_S;
__device__ double g_diff;
__device__ double g_part0;

__global__ void zero_kernel() {
    int t = threadIdx.x;
    if (t < HDIM) g_mu[t] = 0.0;
    if (t == 0) { g_S = 0.0; g_diff = 0.0; g_part0 = 0.0; }
}

// ---------------- tf32 split helpers ----------------
__device__ __forceinline__ unsigned f2tf(float x) {
    unsigned r;
    asm("cvt.rna.tf32.f32 %0, %1;" : "=r"(r) : "f"(x));
    return r;
}
__device__ __forceinline__ void split_tf(float v, unsigned &hi, unsigned &lo) {
    hi = f2tf(v);
    lo = f2tf(v - __uint_as_float(hi));
}
__device__ __forceinline__ void mma8(float* c,
                                     unsigned a0, unsigned a1, unsigned a2, unsigned a3,
                                     unsigned b0, unsigned b1) {
    asm volatile(
        "mma.sync.aligned.m16n8k8.row.col.f32.tf32.tf32.f32 "
        "{%0,%1,%2,%3}, {%4,%5,%6,%7}, {%8,%9}, {%0,%1,%2,%3};"
        : "+f"(c[0]), "+f"(c[1]), "+f"(c[2]), "+f"(c[3])
        : "r"(a0), "r"(a1), "r"(a2), "r"(a3), "r"(b0), "r"(b1));
}

// Warp GEMM over NT n-tiles of 8, K consumed 8 per step.
// A: smem, row-major [m][k], stride LDA, warp's 16 rows at base.
// B: smem, row-major [n][k] (i.e. W[c][k]), stride LDB, warp's n0 at base.
// acc[t][0..3] are the m16n8 C fragments.  3x split-tf32 MMA per tile.
template<int NT, int LDA, int LDB>
__device__ __forceinline__ void gemm_tiles(float (*acc)[4],
                                           const float* __restrict__ A,
                                           const float* __restrict__ B,
                                           int ksteps, int g, int tg)
{
    for (int ks = 0; ks < ksteps; ks++) {
        const int k0 = ks * 8;
        unsigned ah[4], al[4];
        split_tf(A[ g      * LDA + k0 + tg    ], ah[0], al[0]);
        split_tf(A[(g + 8) * LDA + k0 + tg    ], ah[1], al[1]);
        split_tf(A[ g      * LDA + k0 + tg + 4], ah[2], al[2]);
        split_tf(A[(g + 8) * LDA + k0 + tg + 4], ah[3], al[3]);
        #pragma unroll
        for (int t = 0; t < NT; t++) {
            const float* Bp = B + (t * 8 + g) * LDB + k0 + tg;
            unsigned bh0, bl0, bh1, bl1;
            split_tf(Bp[0], bh0, bl0);
            split_tf(Bp[4], bh1, bl1);
            mma8(acc[t], ah[0], ah[1], ah[2], ah[3], bh0, bh1);
            mma8(acc[t], ah[0], ah[1], ah[2], ah[3], bl0, bl1);
            mma8(acc[t], al[0], al[1], al[2], al[3], bh0, bh1);
        }
    }
}

template<int NT>
__device__ __forceinline__ void init_bias(float (*acc)[4], const float* __restrict__ bias,
                                          int n0, int tg, int nvalid)
{
    #pragma unroll
    for (int t = 0; t < NT; t++) {
        int c = n0 + t * 8 + tg * 2;
        float2 bv = make_float2(0.f, 0.f);
        if (c < nvalid) bv = *(const float2*)&bias[c];
        acc[t][0] = bv.x; acc[t][2] = bv.x;
        acc[t][1] = bv.y; acc[t][3] = bv.y;
    }
}

template<int NT>
__device__ __forceinline__ void store_relu(float (*acc)[4], float* __restrict__ H, int ldh,
                                           int m0, int n0, int g, int tg, int nvalid)
{
    #pragma unroll
    for (int t = 0; t < NT; t++) {
        int c = n0 + t * 8 + tg * 2;
        if (c < nvalid) {
            float2 v0 = make_float2(fmaxf(acc[t][0], 0.f), fmaxf(acc[t][1], 0.f));
            float2 v1 = make_float2(fmaxf(acc[t][2], 0.f), fmaxf(acc[t][3], 0.f));
            *(float2*)&H[(m0 + g    ) * ldh + c] = v0;
            *(float2*)&H[(m0 + g + 8) * ldh + c] = v1;
        }
    }
}

__global__ __launch_bounds__(TH, 1)
void mlp_kernel(const float* __restrict__ input,
                const float* __restrict__ h,
                const float* __restrict__ W1,  const float* __restrict__ b1,
                const float* __restrict__ W12, const float* __restrict__ b12,
                const float* __restrict__ W13, const float* __restrict__ b13,
                const float* __restrict__ W2,  const float* __restrict__ b2,
                float* __restrict__ out)
{
    extern __shared__ float smem[];
    float* xS  = smem + H2_OFF;   // layer1 A chunks (64 x 68), dead before h2 written
    float* h2S = smem + H2_OFF;   // 64 x 108
    float* h3S = smem + H3_OFF;   // 64 x 108
    float* h1S = smem + H1_OFF;   // 64 x 212
    float* wS  = smem + WS_OFF;   // weight staging

    const int tid  = threadIdx.x;
    const int lane = tid & 31;
    const int wid  = tid >> 5;
    const int g    = lane >> 2;    // fragment group row 0..7
    const int tg   = lane & 3;     // thread-in-group 0..3
    const int rowg = wid >> 1;     // 0..3 -> 16-row group
    const int nh   = wid & 1;      // n-half
    const int m0   = rowg * 16;
    const int row0 = blockIdx.x * ROWS;

    const float4 z4 = make_float4(0.f, 0.f, 0.f, 0.f);

    float acc[13][4];

    // ===================== Layer 1: [64x768] @ W1^T -> relu [64x200] =====================
    if (nh == 0) init_bias<13>(acc, b1, 0,   tg, D1);
    else         init_bias<12>(acc, b1, 104, tg, D1);

    #pragma unroll 1
    for (int ch = 0; ch < 12; ch++) {
        const int k0 = ch * 64;
        __syncthreads();
        // stage x chunk (64 x 64, stride 68).  Chunks 0-7 come from input, 8-11 from h.
        {
            const float* src; int ss;
            if (k0 < PDIM) { src = input + (size_t)row0 * PDIM + k0; ss = PDIM; }
            else           { src = h     + (size_t)row0 * HDIM + (k0 - PDIM); ss = HDIM; }
            #pragma unroll 1
            for (int i = tid; i < 64 * 16; i += TH) {
                int r = i >> 4, q = i & 15;
                *(float4*)&xS[r * 68 + q * 4] = *(const float4*)(src + (size_t)r * ss + q * 4);
            }
        }
        // stage W1 chunk (200 x 64, stride 68)
        #pragma unroll 1
        for (int i = tid; i < 200 * 16; i += TH) {
            int c = i >> 4, q = i & 15;
            *(float4*)&wS[c * 68 + q * 4] = *(const float4*)(W1 + (size_t)c * DIN + k0 + q * 4);
        }
        __syncthreads();
        if (nh == 0) gemm_tiles<13, 68, 68>(acc, xS + m0 * 68, wS,            8, g, tg);
        else         gemm_tiles<12, 68, 68>(acc, xS + m0 * 68, wS + 104 * 68, 8, g, tg);
    }
    if (nh == 0) store_relu<13>(acc, h1S, 212, m0, 0,   g, tg, D1);
    else         store_relu<12>(acc, h1S, 212, m0, 104, g, tg, D1);
    __syncthreads();

    // zero k-pad cols 100..107 of h2S / h3S (xS is dead now), stage W12 whole (104 x 200, stride 204)
    for (int i = tid; i < 128; i += TH) {
        int r = i & 63;
        float* base = ((i < 64) ? h2S : h3S) + r * 108 + 100;
        *(float4*)base = z4; *(float4*)(base + 4) = z4;
    }
    #pragma unroll 1
    for (int i = tid; i < 104 * 50; i += TH) {
        int c = i / 50, q = i % 50;
        float4 v = z4;
        if (c < D2) v = *(const float4*)(W12 + (size_t)c * D1 + q * 4);
        *(float4*)&wS[c * 204 + q * 4] = v;
    }
    __syncthreads();

    // ===================== Layer 2: [64x200] @ W12^T -> relu [64x100] =====================
    if (nh == 0) {
        init_bias<7>(acc, b12, 0, tg, D2);
        gemm_tiles<7, 212, 204>(acc, h1S + m0 * 212, wS, 25, g, tg);
        store_relu<7>(acc, h2S, 108, m0, 0, g, tg, D2);
    } else {
        init_bias<6>(acc, b12, 56, tg, D2);
        gemm_tiles<6, 212, 204>(acc, h1S + m0 * 212, wS + 56 * 204, 25, g, tg);
        store_relu<6>(acc, h2S, 108, m0, 56, g, tg, D2);
    }
    __syncthreads();

    // stage W13 (104 x 108, zero-padded rows>=100 and k>=100)
    #pragma unroll 1
    for (int i = tid; i < 104 * 27; i += TH) {
        int c = i / 27, q = i % 27;
        float4 v = z4;
        if (c < D3 && q < 25) v = *(const float4*)(W13 + (size_t)c * D2 + q * 4);
        *(float4*)&wS[c * 108 + q * 4] = v;
    }
    __syncthreads();

    // ===================== Layer 3: [64x100] @ W13^T -> relu [64x100] =====================
    if (nh == 0) {
        init_bias<7>(acc, b13, 0, tg, D3);
        gemm_tiles<7, 108, 108>(acc, h2S + m0 * 108, wS, 13, g, tg);
        store_relu<7>(acc, h3S, 108, m0, 0, g, tg, D3);
    } else {
        init_bias<6>(acc, b13, 56, tg, D3);
        gemm_tiles<6, 108, 108>(acc, h2S + m0 * 108, wS + 56 * 108, 13, g, tg);
        store_relu<6>(acc, h3S, 108, m0, 56, g, tg, D3);
    }
    __syncthreads();

    // ===================== Layer 4: [64x100] @ W2^T + b2 -> [64x512], fused part0 ==========
    float dd = 0.f;
    #pragma unroll 1
    for (int ch4 = 0; ch4 < 4; ch4++) {
        // stage W2 n-chunk (128 x 108, k zero-padded 100..107)
        #pragma unroll 1
        for (int i = tid; i < 128 * 27; i += TH) {
            int c = i / 27, q = i % 27;
            float4 v = z4;
            if (q < 25) v = *(const float4*)(W2 + (size_t)(ch4 * 128 + c) * D3 + q * 4);
            *(float4*)&wS[c * 108 + q * 4] = v;
        }
        __syncthreads();

        init_bias<8>(acc, b2, ch4 * 128 + nh * 64, tg, DOUT);
        gemm_tiles<8, 108, 108>(acc, h3S + m0 * 108, wS + nh * 64 * 108, 13, g, tg);

        #pragma unroll
        for (int t = 0; t < 8; t++) {
            int c  = ch4 * 128 + nh * 64 + t * 8 + tg * 2;
            int r1 = row0 + m0 + g;
            int r2 = r1 + 8;
            float2 v0 = make_float2(acc[t][0], acc[t][1]);
            float2 v1 = make_float2(acc[t][2], acc[t][3]);
            *(float2*)&out[(size_t)r1 * PDIM + c] = v0;
            *(float2*)&out[(size_t)r2 * PDIM + c] = v1;
            if (r1 < NROWS - 1) {
                float2 nx = *(const float2*)&input[(size_t)(r1 + 1) * PDIM + c];
                float d0 = v0.x - nx.x, d1 = v0.y - nx.y;
                dd += d0 * d0 + d1 * d1;
            }
            if (r2 < NROWS - 1) {
                float2 nx = *(const float2*)&input[(size_t)(r2 + 1) * PDIM + c];
                float d0 = v1.x - nx.x, d1 = v1.y - nx.y;
                dd += d0 * d0 + d1 * d1;
            }
        }
        __syncthreads();   // protect wS restage next iter
    }

    // reduce dd -> g_part0
    #pragma unroll
    for (int off = 16; off > 0; off >>= 1)
        dd += __shfl_down_sync(0xFFFFFFFFu, dd, off);
    __shared__ float wdd[8];
    if (lane == 0) wdd[wid] = dd;
    __syncthreads();
    if (tid == 0) {
        float s = 0.f;
        #pragma unroll
        for (int w = 0; w < 8; w++) s += wdd[w];
        atomicAdd(&g_part0, (double)s);
    }
}

// h statistics: column sums (mu), sum of squares (S), total variation (diff)
__global__ __launch_bounds__(HDIM)
void hred_kernel(const float* __restrict__ h)
{
    const int c  = threadIdx.x;
    const int r0 = blockIdx.x * 256;
    float prev = (r0 > 0) ? h[(size_t)(r0 - 1) * HDIM + c] : 0.f;
    float cs = 0.f, sq = 0.f, df = 0.f;
    #pragma unroll 4
    for (int i = 0; i < 256; i++) {
        float v = h[(size_t)(r0 + i) * HDIM + c];
        cs += v;
        sq += v * v;
        if (r0 + i > 0) df += fabsf(v - prev);
        prev = v;
    }
    atomicAdd(&g_mu[c], (double)cs);

    #pragma unroll
    for (int off = 16; off > 0; off >>= 1) {
        sq += __shfl_down_sync(0xFFFFFFFFu, sq, off);
        df += __shfl_down_sync(0xFFFFFFFFu, df, off);
    }
    __shared__ float wsq[8], wdf[8];
    int tx = c & 31, ty = c >> 5;
    if (tx == 0) { wsq[ty] = sq; wdf[ty] = df; }
    __syncthreads();
    if (c == 0) {
        float s1 = 0.f, s2 = 0.f;
        #pragma unroll
        for (int w = 0; w < 8; w++) { s1 += wsq[w]; s2 += wdf[w]; }
        atomicAdd(&g_S, (double)s1);
        atomicAdd(&g_diff, (double)s2);
    }
}

__global__ void finalize_kernel(float* __restrict__ out, long long base)
{
    __shared__ double red[HDIM];
    int t = threadIdx.x;
    red[t] = fabs(g_mu[t]);
    __syncthreads();
    for (int s = 128; s > 0; s >>= 1) {
        if (t < s) red[t] += red[t + s];
        __syncthreads();
    }
    if (t == 0) {
        const double Nn = (double)NROWS;
        out[base + 0] = (float)(sqrt(g_part0) / (Nn - 1.0));
        out[base + 1] = (float)(red[0] / Nn / (double)HDIM);
        out[base + 2] = (float)fabs(g_S / Nn / (double)HDIM - 1.0);
        out[base + 3] = (float)(g_diff / (Nn - 1.0) / (double)HDIM);
    }
}

extern "C" void kernel_launch(void* const* d_in, const int* in_sizes, int n_in,
                              void* d_out, int out_size)
{
    const float* input = (const float*)d_in[0];
    const float* h     = (const float*)d_in[1];
    const float* W1    = (const float*)d_in[2];
    const float* b1    = (const float*)d_in[3];
    const float* W12   = (const float*)d_in[4];
    const float* b12   = (const float*)d_in[5];
    const float* W13   = (const float*)d_in[6];
    const float* b13   = (const float*)d_in[7];
    const float* W2    = (const float*)d_in[8];
    const float* b2    = (const float*)d_in[9];
    float* out = (float*)d_out;

    cudaFuncSetAttribute(mlp_kernel, cudaFuncAttributeMaxDynamicSharedMemorySize, SMEM_BYTES);

    zero_kernel<<<1, 256>>>();
    mlp_kernel<<<NROWS / ROWS, TH, SMEM_BYTES>>>(input, h, W1, b1, W12, b12,
                                                 W13, b13, W2, b2, out);
    hred_kernel<<<NROWS / 256, HDIM>>>(h);
    finalize_kernel<<<1, HDIM>>>(out, (long long)out_size - 4);
}

// round 7
// speedup vs baseline: 3.0223x; 1.3525x over previous
#include <cuda_runtime.h>
#include <math.h>

// Problem constants
#define NROWS 65536
#define PDIM  512
#define HDIM  256
#define DIN   768
#define D1    200
#define D2    100
#define D3    100
#define DOUT  512

#define ROWS  64      // rows per block
#define TH    512     // threads per block (16 warps: 4 row-groups x 4 n-quarters)

// Shared memory layout (floats). h2S aliases xS (x dead before h2 written).
// All pitches mod 32 in {4,12,20} -> conflict-free LDS.32 fragment loads.
#define H2_OFF   0                      // 64 x 108 (also xS: 64 x 68)
#define H2_SZ    (64*108)               // 6912
#define H3_OFF   (H2_OFF + H2_SZ)       // 6912 : 64 x 108
#define H3_SZ    (64*108)
#define H1_OFF   (H3_OFF + H3_SZ)       // 13824 : 64 x 212
#define H1_SZ    (64*212)               // 13568
#define WS_OFF   (H1_OFF + H1_SZ)       // 27392
#define PLANE    13824                  // max weight plane (128x108 / 200x68)
#define SMEM_F   (WS_OFF + 2*PLANE)     // 55040
#define SMEM_BYTES (SMEM_F * 4)         // 220160

// Global accumulators
__device__ double g_mu[HDIM];
__device__ double g_S;
__device__ double g_diff;
__device__ double g_part0;

__global__ void zero_kernel() {
    int t = threadIdx.x;
    if (t < HDIM) g_mu[t] = 0.0;
    if (t == 0) { g_S = 0.0; g_diff = 0.0; g_part0 = 0.0; }
}

// no-op: shifts ncu capture slot onto mlp_kernel
__global__ void dummy_kernel() {}

// ---------------- tf32 split helpers ----------------
__device__ __forceinline__ unsigned f2tf(float x) {
    unsigned r;
    asm("cvt.rna.tf32.f32 %0, %1;" : "=r"(r) : "f"(x));
    return r;
}
__device__ __forceinline__ void split_tf(float v, unsigned &hi, unsigned &lo) {
    hi = f2tf(v);
    lo = f2tf(v - __uint_as_float(hi));
}
// split float4 -> hi/lo float4 (values are tf32-exact floats)
__device__ __forceinline__ void split4(float4 w, float4 &h4, float4 &l4) {
    unsigned h, l;
    split_tf(w.x, h, l); h4.x = __uint_as_float(h); l4.x = __uint_as_float(l);
    split_tf(w.y, h, l); h4.y = __uint_as_float(h); l4.y = __uint_as_float(l);
    split_tf(w.z, h, l); h4.z = __uint_as_float(h); l4.z = __uint_as_float(l);
    split_tf(w.w, h, l); h4.w = __uint_as_float(h); l4.w = __uint_as_float(l);
}
__device__ __forceinline__ void mma8(float* c,
                                     unsigned a0, unsigned a1, unsigned a2, unsigned a3,
                                     unsigned b0, unsigned b1) {
    asm volatile(
        "mma.sync.aligned.m16n8k8.row.col.f32.tf32.tf32.f32 "
        "{%0,%1,%2,%3}, {%4,%5,%6,%7}, {%8,%9}, {%0,%1,%2,%3};"
        : "+f"(c[0]), "+f"(c[1]), "+f"(c[2]), "+f"(c[3])
        : "r"(a0), "r"(a1), "r"(a2), "r"(a3), "r"(b0), "r"(b1));
}

// Warp GEMM: A split on the fly (amortized over NT tiles), B pre-split planes.
// Inner tile work = 4 LDS + 3 MMA, no CVT.
template<int NT, int LDA, int LDB>
__device__ __forceinline__ void gemm_p(float (*acc)[4],
                                       const float* __restrict__ A,
                                       const float* __restrict__ Bh,
                                       const float* __restrict__ Bl,
                                       int ksteps, int g, int tg)
{
    for (int ks = 0; ks < ksteps; ks++) {
        const int k0 = ks * 8;
        unsigned ah[4], al[4];
        split_tf(A[ g      * LDA + k0 + tg    ], ah[0], al[0]);
        split_tf(A[(g + 8) * LDA + k0 + tg    ], ah[1], al[1]);
        split_tf(A[ g      * LDA + k0 + tg + 4], ah[2], al[2]);
        split_tf(A[(g + 8) * LDA + k0 + tg + 4], ah[3], al[3]);
        #pragma unroll
        for (int t = 0; t < NT; t++) {
            const int bo = (t * 8 + g) * LDB + k0 + tg;
            unsigned bh0 = __float_as_uint(Bh[bo]), bh1 = __float_as_uint(Bh[bo + 4]);
            unsigned bl0 = __float_as_uint(Bl[bo]), bl1 = __float_as_uint(Bl[bo + 4]);
            mma8(acc[t], ah[0], ah[1], ah[2], ah[3], bh0, bh1);
            mma8(acc[t], ah[0], ah[1], ah[2], ah[3], bl0, bl1);
            mma8(acc[t], al[0], al[1], al[2], al[3], bh0, bh1);
        }
    }
}

template<int NT>
__device__ __forceinline__ void init_bias(float (*acc)[4], const float* __restrict__ bias,
                                          int n0, int tg, int nvalid)
{
    #pragma unroll
    for (int t = 0; t < NT; t++) {
        int c = n0 + t * 8 + tg * 2;
        float2 bv = make_float2(0.f, 0.f);
        if (c < nvalid) bv = *(const float2*)&bias[c];
        acc[t][0] = bv.x; acc[t][2] = bv.x;
        acc[t][1] = bv.y; acc[t][3] = bv.y;
    }
}

template<int NT>
__device__ __forceinline__ void store_relu(float (*acc)[4], float* __restrict__ H, int ldh,
                                           int m0, int n0, int g, int tg, int nvalid)
{
    #pragma unroll
    for (int t = 0; t < NT; t++) {
        int c = n0 + t * 8 + tg * 2;
        if (c < nvalid) {
            float2 v0 = make_float2(fmaxf(acc[t][0], 0.f), fmaxf(acc[t][1], 0.f));
            float2 v1 = make_float2(fmaxf(acc[t][2], 0.f), fmaxf(acc[t][3], 0.f));
            *(float2*)&H[(m0 + g    ) * ldh + c] = v0;
            *(float2*)&H[(m0 + g + 8) * ldh + c] = v1;
        }
    }
}

__global__ __launch_bounds__(TH, 1)
void mlp_kernel(const float* __restrict__ input,
                const float* __restrict__ h,
                const float* __restrict__ W1,  const float* __restrict__ b1,
                const float* __restrict__ W12, const float* __restrict__ b12,
                const float* __restrict__ W13, const float* __restrict__ b13,
                const float* __restrict__ W2,  const float* __restrict__ b2,
                float* __restrict__ out)
{
    extern __shared__ float smem[];
    float* xS  = smem + H2_OFF;   // layer1 A chunks (64 x 68)
    float* h2S = smem + H2_OFF;   // 64 x 108
    float* h3S = smem + H3_OFF;   // 64 x 108
    float* h1S = smem + H1_OFF;   // 64 x 212
    float* wHi = smem + WS_OFF;   // weight hi plane
    float* wLo = smem + WS_OFF + PLANE;

    const int tid  = threadIdx.x;
    const int lane = tid & 31;
    const int wid  = tid >> 5;     // 0..15
    const int g    = lane >> 2;
    const int tg   = lane & 3;
    const int rowg = wid >> 2;     // 0..3
    const int nq   = wid & 3;      // n-quarter
    const int m0   = rowg * 16;
    const int row0 = blockIdx.x * ROWS;

    const float4 z4 = make_float4(0.f, 0.f, 0.f, 0.f);

    float acc[7][4];

    // Layer-1 n-quarter assignment over 25 tiles (200 cols): {7,6,6,6}
    const int L1_NT[4] = {7, 6, 6, 6};
    const int L1_N0[4] = {0, 56, 104, 152};
    // Layers 2/3 over 13 tiles (104 cols incl pad): {4,3,3,3}
    const int L23_N0[4] = {0, 32, 56, 80};

    // ===================== Layer 1: [64x768] @ W1^T -> relu [64x200] =====================
    if (nq == 0) init_bias<7>(acc, b1, 0, tg, D1);
    else         init_bias<6>(acc, b1, L1_N0[nq], tg, D1);

    #pragma unroll 1
    for (int ch = 0; ch < 12; ch++) {
        const int k0 = ch * 64;
        __syncthreads();
        // stage x chunk (64 x 64, pitch 68), fp32
        {
            const float* src; int ss;
            if (k0 < PDIM) { src = input + (size_t)row0 * PDIM + k0; ss = PDIM; }
            else           { src = h     + (size_t)row0 * HDIM + (k0 - PDIM); ss = HDIM; }
            #pragma unroll 1
            for (int i = tid; i < 64 * 16; i += TH) {
                int r = i >> 4, q = i & 15;
                *(float4*)&xS[r * 68 + q * 4] = *(const float4*)(src + (size_t)r * ss + q * 4);
            }
        }
        // stage W1 chunk (200 x 64, pitch 68) split into hi/lo planes
        #pragma unroll 1
        for (int i = tid; i < 200 * 16; i += TH) {
            int c = i >> 4, q = i & 15;
            float4 w = *(const float4*)(W1 + (size_t)c * DIN + k0 + q * 4);
            float4 h4, l4; split4(w, h4, l4);
            *(float4*)&wHi[c * 68 + q * 4] = h4;
            *(float4*)&wLo[c * 68 + q * 4] = l4;
        }
        __syncthreads();
        const float* A = xS + m0 * 68;
        if (nq == 0) gemm_p<7, 68, 68>(acc, A, wHi, wLo, 8, g, tg);
        else         gemm_p<6, 68, 68>(acc, A, wHi + L1_N0[nq] * 68, wLo + L1_N0[nq] * 68, 8, g, tg);
    }
    if (nq == 0) store_relu<7>(acc, h1S, 212, m0, 0, g, tg, D1);
    else         store_relu<6>(acc, h1S, 212, m0, L1_N0[nq], g, tg, D1);
    __syncthreads();

    // zero k-pad cols 100..107 of h2S / h3S (xS dead now)
    for (int i = tid; i < 128; i += TH) {
        int r = i & 63;
        float* base = ((i < 64) ? h2S : h3S) + r * 108 + 100;
        *(float4*)base = z4; *(float4*)(base + 4) = z4;
    }

    // ===================== Layer 2: [64x200] @ W12^T -> relu [64x100] =====================
    {
        const int NTq = (nq == 0) ? 4 : 3;
        if (nq == 0) init_bias<4>(acc, b12, 0, tg, D2);
        else         init_bias<3>(acc, b12, L23_N0[nq], tg, D2);

        // chunk a: k [0,104), pitch 108, 13 ksteps
        #pragma unroll 1
        for (int i = tid; i < 104 * 26; i += TH) {
            int c = i / 26, q = i % 26;
            float4 w = z4;
            if (c < D2) w = *(const float4*)(W12 + (size_t)c * D1 + q * 4);
            float4 h4, l4; split4(w, h4, l4);
            *(float4*)&wHi[c * 108 + q * 4] = h4;
            *(float4*)&wLo[c * 108 + q * 4] = l4;
        }
        __syncthreads();
        {
            const float* A = h1S + m0 * 212;
            int o = L23_N0[nq] * 108;
            if (NTq == 4) gemm_p<4, 212, 108>(acc, A, wHi + o, wLo + o, 13, g, tg);
            else          gemm_p<3, 212, 108>(acc, A, wHi + o, wLo + o, 13, g, tg);
        }
        __syncthreads();
        // chunk b: k [104,200), pitch 100, 12 ksteps
        #pragma unroll 1
        for (int i = tid; i < 104 * 24; i += TH) {
            int c = i / 24, q = i % 24;
            float4 w = z4;
            if (c < D2) w = *(const float4*)(W12 + (size_t)c * D1 + 104 + q * 4);
            float4 h4, l4; split4(w, h4, l4);
            *(float4*)&wHi[c * 100 + q * 4] = h4;
            *(float4*)&wLo[c * 100 + q * 4] = l4;
        }
        __syncthreads();
        {
            const float* A = h1S + m0 * 212 + 104;
            int o = L23_N0[nq] * 100;
            if (NTq == 4) gemm_p<4, 212, 100>(acc, A, wHi + o, wLo + o, 12, g, tg);
            else          gemm_p<3, 212, 100>(acc, A, wHi + o, wLo + o, 12, g, tg);
        }
        if (NTq == 4) store_relu<4>(acc, h2S, 108, m0, 0, g, tg, D2);
        else          store_relu<3>(acc, h2S, 108, m0, L23_N0[nq], g, tg, D2);
    }
    __syncthreads();

    // ===================== Layer 3: [64x100] @ W13^T -> relu [64x100] =====================
    {
        // stage W13 (104 x 104, pitch 108, zero pad rows>=100 and k>=100)
        #pragma unroll 1
        for (int i = tid; i < 104 * 26; i += TH) {
            int c = i / 26, q = i % 26;
            float4 w = z4;
            if (c < D3 && q < 25) w = *(const float4*)(W13 + (size_t)c * D2 + q * 4);
            float4 h4, l4; split4(w, h4, l4);
            *(float4*)&wHi[c * 108 + q * 4] = h4;
            *(float4*)&wLo[c * 108 + q * 4] = l4;
        }
        __syncthreads();
        const float* A = h2S + m0 * 108;
        int o = L23_N0[nq] * 108;
        if (nq == 0) {
            init_bias<4>(acc, b13, 0, tg, D3);
            gemm_p<4, 108, 108>(acc, A, wHi + o, wLo + o, 13, g, tg);
            store_relu<4>(acc, h3S, 108, m0, 0, g, tg, D3);
        } else {
            init_bias<3>(acc, b13, L23_N0[nq], tg, D3);
            gemm_p<3, 108, 108>(acc, A, wHi + o, wLo + o, 13, g, tg);
            store_relu<3>(acc, h3S, 108, m0, L23_N0[nq], g, tg, D3);
        }
    }
    __syncthreads();

    // ===================== Layer 4: [64x100] @ W2^T + b2 -> [64x512], fused part0 ==========
    float dd = 0.f;
    #pragma unroll 1
    for (int ch4 = 0; ch4 < 4; ch4++) {
        // stage W2 n-chunk (128 x 104, pitch 108, k zero-padded 100..103)
        #pragma unroll 1
        for (int i = tid; i < 128 * 26; i += TH) {
            int c = i / 26, q = i % 26;
            float4 w = z4;
            if (q < 25) w = *(const float4*)(W2 + (size_t)(ch4 * 128 + c) * D3 + q * 4);
            float4 h4, l4; split4(w, h4, l4);
            *(float4*)&wHi[c * 108 + q * 4] = h4;
            *(float4*)&wLo[c * 108 + q * 4] = l4;
        }
        __syncthreads();

        init_bias<4>(acc, b2, ch4 * 128 + nq * 32, tg, DOUT);
        {
            const float* A = h3S + m0 * 108;
            int o = nq * 32 * 108;
            gemm_p<4, 108, 108>(acc, A, wHi + o, wLo + o, 13, g, tg);
        }

        #pragma unroll
        for (int t = 0; t < 4; t++) {
            int c  = ch4 * 128 + nq * 32 + t * 8 + tg * 2;
            int r1 = row0 + m0 + g;
            int r2 = r1 + 8;
            float2 v0 = make_float2(acc[t][0], acc[t][1]);
            float2 v1 = make_float2(acc[t][2], acc[t][3]);
            *(float2*)&out[(size_t)r1 * PDIM + c] = v0;
            *(float2*)&out[(size_t)r2 * PDIM + c] = v1;
            if (r1 < NROWS - 1) {
                float2 nx = *(const float2*)&input[(size_t)(r1 + 1) * PDIM + c];
                float d0 = v0.x - nx.x, d1 = v0.y - nx.y;
                dd += d0 * d0 + d1 * d1;
            }
            if (r2 < NROWS - 1) {
                float2 nx = *(const float2*)&input[(size_t)(r2 + 1) * PDIM + c];
                float d0 = v1.x - nx.x, d1 = v1.y - nx.y;
                dd += d0 * d0 + d1 * d1;
            }
        }
        __syncthreads();   // protect wS restage next iter
    }

    // reduce dd -> g_part0
    #pragma unroll
    for (int off = 16; off > 0; off >>= 1)
        dd += __shfl_down_sync(0xFFFFFFFFu, dd, off);
    __shared__ float wdd[16];
    if (lane == 0) wdd[wid] = dd;
    __syncthreads();
    if (tid == 0) {
        float s = 0.f;
        #pragma unroll
        for (int w = 0; w < 16; w++) s += wdd[w];
        atomicAdd(&g_part0, (double)s);
    }
}

// h statistics: column sums (mu), sum of squares (S), total variation (diff)
__global__ __launch_bounds__(HDIM)
void hred_kernel(const float* __restrict__ h)
{
    const int c  = threadIdx.x;
    const int r0 = blockIdx.x * 256;
    float prev = (r0 > 0) ? h[(size_t)(r0 - 1) * HDIM + c] : 0.f;
    float cs = 0.f, sq = 0.f, df = 0.f;
    #pragma unroll 4
    for (int i = 0; i < 256; i++) {
        float v = h[(size_t)(r0 + i) * HDIM + c];
        cs += v;
        sq += v * v;
        if (r0 + i > 0) df += fabsf(v - prev);
        prev = v;
    }
    atomicAdd(&g_mu[c], (double)cs);

    #pragma unroll
    for (int off = 16; off > 0; off >>= 1) {
        sq += __shfl_down_sync(0xFFFFFFFFu, sq, off);
        df += __shfl_down_sync(0xFFFFFFFFu, df, off);
    }
    __shared__ float wsq[8], wdf[8];
    int tx = c & 31, ty = c >> 5;
    if (tx == 0) { wsq[ty] = sq; wdf[ty] = df; }
    __syncthreads();
    if (c == 0) {
        float s1 = 0.f, s2 = 0.f;
        #pragma unroll
        for (int w = 0; w < 8; w++) { s1 += wsq[w]; s2 += wdf[w]; }
        atomicAdd(&g_S, (double)s1);
        atomicAdd(&g_diff, (double)s2);
    }
}

__global__ void finalize_kernel(float* __restrict__ out, long long base)
{
    __shared__ double red[HDIM];
    int t = threadIdx.x;
    red[t] = fabs(g_mu[t]);
    __syncthreads();
    for (int s = 128; s > 0; s >>= 1) {
        if (t < s) red[t] += red[t + s];
        __syncthreads();
    }
    if (t == 0) {
        const double Nn = (double)NROWS;
        out[base + 0] = (float)(sqrt(g_part0) / (Nn - 1.0));
        out[base + 1] = (float)(red[0] / Nn / (double)HDIM);
        out[base + 2] = (float)fabs(g_S / Nn / (double)HDIM - 1.0);
        out[base + 3] = (float)(g_diff / (Nn - 1.0) / (double)HDIM);
    }
}

extern "C" void kernel_launch(void* const* d_in, const int* in_sizes, int n_in,
                              void* d_out, int out_size)
{
    const float* input = (const float*)d_in[0];
    const float* h     = (const float*)d_in[1];
    const float* W1    = (const float*)d_in[2];
    const float* b1    = (const float*)d_in[3];
    const float* W12   = (const float*)d_in[4];
    const float* b12   = (const float*)d_in[5];
    const float* W13   = (const float*)d_in[6];
    const float* b13   = (const float*)d_in[7];
    const float* W2    = (const float*)d_in[8];
    const float* b2    = (const float*)d_in[9];
    float* out = (float*)d_out;

    cudaFuncSetAttribute(mlp_kernel, cudaFuncAttributeMaxDynamicSharedMemorySize, SMEM_BYTES);

    zero_kernel<<<1, 256>>>();
    hred_kernel<<<NROWS / 256, HDIM>>>(h);
    dummy_kernel<<<1, 32>>>();
    mlp_kernel<<<NROWS / ROWS, TH, SMEM_BYTES>>>(input, h, W1, b1, W12, b12,
                                                 W13, b13, W2, b2, out);
    finalize_kernel<<<1, HDIM>>>(out, (long long)out_size - 4);
}

// round 12
// speedup vs baseline: 3.9465x; 1.3058x over previous
#include <cuda_runtime.h>
#include <cuda_bf16.h>
#include <math.h>

// Problem constants
#define NROWS 65536
#define PDIM  512
#define HDIM  256
#define DIN   768
#define D1    200
#define D2    100
#define D3    100
#define DOUT  512

#define ROWS  64      // rows per block
#define TH    512     // threads per block (16 warps: 4 row-groups x 4 n-quarters)

// ---- SMEM layout in u32 words.  All data stored as packed bf16x2 (hi/lo planes).
// Word pitches mod 32 in {4,12,20,28} -> conflict-free LDS.32 fragment loads.
#define H2PL    (64*60)                 // 3840 words per plane (k words 56 used, pitch 60)
#define H2_OFF  0                       // h2 hi/lo; also aliases x chunk planes (64x36 each)
#define H3_OFF  (H2_OFF + 2*H2PL)       // 7680
#define H1PL    (64*108)                // 6912
#define H1_OFF  (H3_OFF + 2*H2PL)       // 15360
#define WS_OFF  (H1_OFF + 2*H1PL)       // 29184
#define WPL     11232                   // max weight plane: W12 104x108
#define SMEM_U32 (WS_OFF + 2*WPL)       // 51648
#define SMEM_BYTES (SMEM_U32 * 4)       // 206592

// Global accumulators
__device__ double g_mu[HDIM];
__device__ double g_S;
__device__ double g_diff;
__device__ double g_part0;

__global__ void zero_kernel() {
    int t = threadIdx.x;
    if (t < HDIM) g_mu[t] = 0.0;
    if (t == 0) { g_S = 0.0; g_diff = 0.0; g_part0 = 0.0; }
}

// no-op: keeps ncu capture slot aligned on mlp_kernel
__global__ void dummy_kernel() {}

// ---------------- bf16 split helpers ----------------
// split2: (a,b) -> packed hi bf16x2 word + packed lo bf16x2 word (3-term split source)
__device__ __forceinline__ void split2(float a, float b, unsigned &hi, unsigned &lo) {
    __nv_bfloat16 ha = __float2bfloat16_rn(a);
    __nv_bfloat16 hb = __float2bfloat16_rn(b);
    float la = a - __bfloat162float(ha);
    float lb = b - __bfloat162float(hb);
    __nv_bfloat162 hp; hp.x = ha; hp.y = hb;
    __nv_bfloat162 lp; lp.x = __float2bfloat16_rn(la); lp.y = __float2bfloat16_rn(lb);
    hi = *reinterpret_cast<unsigned*>(&hp);
    lo = *reinterpret_cast<unsigned*>(&lp);
}
// float4 (4 consecutive k) -> uint2 hi words + uint2 lo words
__device__ __forceinline__ void split4w(float4 v, uint2 &h2v, uint2 &l2v) {
    split2(v.x, v.y, h2v.x, l2v.x);
    split2(v.z, v.w, h2v.y, l2v.y);
}

__device__ __forceinline__ void mma16(float* c,
                                      unsigned a0, unsigned a1, unsigned a2, unsigned a3,
                                      unsigned b0, unsigned b1) {
    asm volatile(
        "mma.sync.aligned.m16n8k16.row.col.f32.bf16.bf16.f32 "
        "{%0,%1,%2,%3}, {%4,%5,%6,%7}, {%8,%9}, {%0,%1,%2,%3};"
        : "+f"(c[0]), "+f"(c[1]), "+f"(c[2]), "+f"(c[3])
        : "r"(a0), "r"(a1), "r"(a2), "r"(a3), "r"(b0), "r"(b1));
}

// Warp GEMM, everything pre-split: inner work = LDS.32 + MMA only.
// A/B planes hold packed bf16x2 along k (word k2 = k/2).  Per k-step: 16 k = 8 words.
template<int NT, int LDA, int LDB>
__device__ __forceinline__ void gemm_bf(float (*acc)[4],
                                        const unsigned* __restrict__ Ah,
                                        const unsigned* __restrict__ Al,
                                        const unsigned* __restrict__ Bh,
                                        const unsigned* __restrict__ Bl,
                                        int ksteps, int g, int tg)
{
    for (int ks = 0; ks < ksteps; ks++) {
        const int w0 = ks * 8;
        const int oA0 =  g      * LDA + w0 + tg;
        const int oA1 = (g + 8) * LDA + w0 + tg;
        unsigned ah0 = Ah[oA0], ah1 = Ah[oA1], ah2 = Ah[oA0 + 4], ah3 = Ah[oA1 + 4];
        unsigned al0 = Al[oA0], al1 = Al[oA1], al2 = Al[oA0 + 4], al3 = Al[oA1 + 4];
        #pragma unroll
        for (int t = 0; t < NT; t++) {
            const int bo = (t * 8 + g) * LDB + w0 + tg;
            unsigned bh0 = Bh[bo], bh1 = Bh[bo + 4];
            unsigned bl0 = Bl[bo], bl1 = Bl[bo + 4];
            mma16(acc[t], ah0, ah1, ah2, ah3, bh0, bh1);
            mma16(acc[t], ah0, ah1, ah2, ah3, bl0, bl1);
            mma16(acc[t], al0, al1, al2, al3, bh0, bh1);
        }
    }
}

template<int NT>
__device__ __forceinline__ void init_bias(float (*acc)[4], const float* __restrict__ bias,
                                          int n0, int tg, int nvalid)
{
    #pragma unroll
    for (int t = 0; t < NT; t++) {
        int c = n0 + t * 8 + tg * 2;
        float2 bv = make_float2(0.f, 0.f);
        if (c < nvalid) bv = *(const float2*)&bias[c];
        acc[t][0] = bv.x; acc[t][2] = bv.x;
        acc[t][1] = bv.y; acc[t][3] = bv.y;
    }
}

// relu + bf16 split + pack: cols (c, c+1) become next layer's k-pair word c/2.
template<int NT>
__device__ __forceinline__ void store_relu_bf(float (*acc)[4],
                                              unsigned* __restrict__ Hh,
                                              unsigned* __restrict__ Hl,
                                              int ldw, int m0, int n0,
                                              int g, int tg, int nvalid)
{
    #pragma unroll
    for (int t = 0; t < NT; t++) {
        int c = n0 + t * 8 + tg * 2;
        if (c < nvalid) {
            unsigned h0, l0, h1, l1;
            split2(fmaxf(acc[t][0], 0.f), fmaxf(acc[t][1], 0.f), h0, l0);
            split2(fmaxf(acc[t][2], 0.f), fmaxf(acc[t][3], 0.f), h1, l1);
            int o0 = (m0 + g) * ldw + (c >> 1);
            int o1 = (m0 + g + 8) * ldw + (c >> 1);
            Hh[o0] = h0; Hl[o0] = l0;
            Hh[o1] = h1; Hl[o1] = l1;
        }
    }
}

__global__ __launch_bounds__(TH, 1)
void mlp_kernel(const float* __restrict__ input,
                const float* __restrict__ h,
                const float* __restrict__ W1,  const float* __restrict__ b1,
                const float* __restrict__ W12, const float* __restrict__ b12,
                const float* __restrict__ W13, const float* __restrict__ b13,
                const float* __restrict__ W2,  const float* __restrict__ b2,
                float* __restrict__ out)
{
    extern __shared__ unsigned smem[];
    unsigned* xHi  = smem + H2_OFF;            // 64 x 36 (layer1 A chunk)
    unsigned* xLo  = xHi + 64 * 36;
    unsigned* h2Hi = smem + H2_OFF;            // 64 x 60
    unsigned* h2Lo = h2Hi + H2PL;
    unsigned* h3Hi = smem + H3_OFF;            // 64 x 60
    unsigned* h3Lo = h3Hi + H2PL;
    unsigned* h1Hi = smem + H1_OFF;            // 64 x 108
    unsigned* h1Lo = h1Hi + H1PL;
    unsigned* wHi  = smem + WS_OFF;
    unsigned* wLo  = wHi + WPL;

    const int tid  = threadIdx.x;
    const int lane = tid & 31;
    const int wid  = tid >> 5;     // 0..15
    const int g    = lane >> 2;
    const int tg   = lane & 3;
    const int rowg = wid >> 2;     // 0..3
    const int nq   = wid & 3;      // n-quarter
    const int m0   = rowg * 16;
    const int row0 = blockIdx.x * ROWS;

    const float4 z4 = make_float4(0.f, 0.f, 0.f, 0.f);

    float acc[7][4];

    // Layer-1: 25 n-tiles -> {7,6,6,6}; layers 2/3: 13 tiles -> {4,3,3,3}
    const int L1_N0[4]  = {0, 56, 104, 152};
    const int L23_N0[4] = {0, 32, 56, 80};

    // ===================== Layer 1: [64x768] @ W1^T -> relu [64x200] =====================
    if (nq == 0) init_bias<7>(acc, b1, 0, tg, D1);
    else         init_bias<6>(acc, b1, L1_N0[nq], tg, D1);

    #pragma unroll 1
    for (int ch = 0; ch < 12; ch++) {
        const int k0 = ch * 64;
        __syncthreads();
        // stage x chunk (64 rows x 64 k -> 32 words, pitch 36), split hi/lo
        {
            const float* src; int ss;
            if (k0 < PDIM) { src = input + (size_t)row0 * PDIM + k0; ss = PDIM; }
            else           { src = h     + (size_t)row0 * HDIM + (k0 - PDIM); ss = HDIM; }
            for (int i = tid; i < 64 * 16; i += TH) {
                int r = i >> 4, q = i & 15;
                float4 v = *(const float4*)(src + (size_t)r * ss + q * 4);
                uint2 hw, lw; split4w(v, hw, lw);
                *(uint2*)&xHi[r * 36 + q * 2] = hw;
                *(uint2*)&xLo[r * 36 + q * 2] = lw;
            }
        }
        // stage W1 chunk (200 n-rows x 64 k -> 32 words, pitch 36), split hi/lo
        for (int i = tid; i < 200 * 16; i += TH) {
            int c = i >> 4, q = i & 15;
            float4 v = *(const float4*)(W1 + (size_t)c * DIN + k0 + q * 4);
            uint2 hw, lw; split4w(v, hw, lw);
            *(uint2*)&wHi[c * 36 + q * 2] = hw;
            *(uint2*)&wLo[c * 36 + q * 2] = lw;
        }
        __syncthreads();
        const unsigned* Ah = xHi + m0 * 36;
        const unsigned* Al = xLo + m0 * 36;
        int o = L1_N0[nq] * 36;
        if (nq == 0) gemm_bf<7, 36, 36>(acc, Ah, Al, wHi, wLo, 4, g, tg);
        else         gemm_bf<6, 36, 36>(acc, Ah, Al, wHi + o, wLo + o, 4, g, tg);
    }
    if (nq == 0) store_relu_bf<7>(acc, h1Hi, h1Lo, 108, m0, 0, g, tg, D1);
    else         store_relu_bf<6>(acc, h1Hi, h1Lo, 108, m0, L1_N0[nq], g, tg, D1);
    __syncthreads();

    // zero k-pad words: h1 words 100..103; h2/h3 words 50..55 (x dead now)
    for (int i = tid; i < 64 * 4; i += TH) {
        int r = i >> 2, w = 100 + (i & 3);
        h1Hi[r * 108 + w] = 0; h1Lo[r * 108 + w] = 0;
    }
    for (int i = tid; i < 64 * 6; i += TH) {
        int r = i / 6, w = 50 + (i % 6);
        h2Hi[r * 60 + w] = 0; h2Lo[r * 60 + w] = 0;
        h3Hi[r * 60 + w] = 0; h3Lo[r * 60 + w] = 0;
    }
    // stage W12 whole: 104 n-rows x 208 k -> 104 words, pitch 108
    for (int i = tid; i < 104 * 52; i += TH) {
        int c = i / 52, q = i % 52;
        float4 v = z4;
        if (c < D2 && q < 50) v = *(const float4*)(W12 + (size_t)c * D1 + q * 4);
        uint2 hw, lw; split4w(v, hw, lw);
        *(uint2*)&wHi[c * 108 + q * 2] = hw;
        *(uint2*)&wLo[c * 108 + q * 2] = lw;
    }
    __syncthreads();

    // ===================== Layer 2: [64x200] @ W12^T -> relu [64x100] =====================
    {
        const unsigned* Ah = h1Hi + m0 * 108;
        const unsigned* Al = h1Lo + m0 * 108;
        int o = L23_N0[nq] * 108;
        if (nq == 0) {
            init_bias<4>(acc, b12, 0, tg, D2);
            gemm_bf<4, 108, 108>(acc, Ah, Al, wHi + o, wLo + o, 13, g, tg);
            store_relu_bf<4>(acc, h2Hi, h2Lo, 60, m0, 0, g, tg, D2);
        } else {
            init_bias<3>(acc, b12, L23_N0[nq], tg, D2);
            gemm_bf<3, 108, 108>(acc, Ah, Al, wHi + o, wLo + o, 13, g, tg);
            store_relu_bf<3>(acc, h2Hi, h2Lo, 60, m0, L23_N0[nq], g, tg, D2);
        }
    }
    __syncthreads();

    // stage W13: 104 n-rows x 112 k -> 56 words, pitch 60
    for (int i = tid; i < 104 * 28; i += TH) {
        int c = i / 28, q = i % 28;
        float4 v = z4;
        if (c < D3 && q < 25) v = *(const float4*)(W13 + (size_t)c * D2 + q * 4);
        uint2 hw, lw; split4w(v, hw, lw);
        *(uint2*)&wHi[c * 60 + q * 2] = hw;
        *(uint2*)&wLo[c * 60 + q * 2] = lw;
    }
    __syncthreads();

    // ===================== Layer 3: [64x100] @ W13^T -> relu [64x100] =====================
    {
        const unsigned* Ah = h2Hi + m0 * 60;
        const unsigned* Al = h2Lo + m0 * 60;
        int o = L23_N0[nq] * 60;
        if (nq == 0) {
            init_bias<4>(acc, b13, 0, tg, D3);
            gemm_bf<4, 60, 60>(acc, Ah, Al, wHi + o, wLo + o, 7, g, tg);
            store_relu_bf<4>(acc, h3Hi, h3Lo, 60, m0, 0, g, tg, D3);
        } else {
            init_bias<3>(acc, b13, L23_N0[nq], tg, D3);
            gemm_bf<3, 60, 60>(acc, Ah, Al, wHi + o, wLo + o, 7, g, tg);
            store_relu_bf<3>(acc, h3Hi, h3Lo, 60, m0, L23_N0[nq], g, tg, D3);
        }
    }
    __syncthreads();

    // ===================== Layer 4: [64x100] @ W2^T + b2 -> [64x512], fused part0 ==========
    float dd = 0.f;
    #pragma unroll 1
    for (int ch4 = 0; ch4 < 4; ch4++) {
        // stage W2 n-chunk: 128 rows x 112 k -> 56 words, pitch 60
        for (int i = tid; i < 128 * 28; i += TH) {
            int c = i / 28, q = i % 28;
            float4 v = z4;
            if (q < 25) v = *(const float4*)(W2 + (size_t)(ch4 * 128 + c) * D3 + q * 4);
            uint2 hw, lw; split4w(v, hw, lw);
            *(uint2*)&wHi[c * 60 + q * 2] = hw;
            *(uint2*)&wLo[c * 60 + q * 2] = lw;
        }
        __syncthreads();

        init_bias<4>(acc, b2, ch4 * 128 + nq * 32, tg, DOUT);
        {
            const unsigned* Ah = h3Hi + m0 * 60;
            const unsigned* Al = h3Lo + m0 * 60;
            int o = nq * 32 * 60;
            gemm_bf<4, 60, 60>(acc, Ah, Al, wHi + o, wLo + o, 7, g, tg);
        }

        #pragma unroll
        for (int t = 0; t < 4; t++) {
            int c  = ch4 * 128 + nq * 32 + t * 8 + tg * 2;
            int r1 = row0 + m0 + g;
            int r2 = r1 + 8;
            float2 v0 = make_float2(acc[t][0], acc[t][1]);
            float2 v1 = make_float2(acc[t][2], acc[t][3]);
            *(float2*)&out[(size_t)r1 * PDIM + c] = v0;
            *(float2*)&out[(size_t)r2 * PDIM + c] = v1;
            if (r1 < NROWS - 1) {
                float2 nx = *(const float2*)&input[(size_t)(r1 + 1) * PDIM + c];
                float d0 = v0.x - nx.x, d1 = v0.y - nx.y;
                dd += d0 * d0 + d1 * d1;
            }
            if (r2 < NROWS - 1) {
                float2 nx = *(const float2*)&input[(size_t)(r2 + 1) * PDIM + c];
                float d0 = v1.x - nx.x, d1 = v1.y - nx.y;
                dd += d0 * d0 + d1 * d1;
            }
        }
        __syncthreads();   // protect wS restage next iter
    }

    // reduce dd -> g_part0
    #pragma unroll
    for (int off = 16; off > 0; off >>= 1)
        dd += __shfl_down_sync(0xFFFFFFFFu, dd, off);
    __shared__ float wdd[16];
    if (lane == 0) wdd[wid] = dd;
    __syncthreads();
    if (tid == 0) {
        float s = 0.f;
        #pragma unroll
        for (int w = 0; w < 16; w++) s += wdd[w];
        atomicAdd(&g_part0, (double)s);
    }
}

// h statistics: column sums (mu), sum of squares (S), total variation (diff)
__global__ __launch_bounds__(HDIM)
void hred_kernel(const float* __restrict__ h)
{
    const int c  = threadIdx.x;
    const int r0 = blockIdx.x * 256;
    float prev = (r0 > 0) ? h[(size_t)(r0 - 1) * HDIM + c] : 0.f;
    float cs = 0.f, sq = 0.f, df = 0.f;
    #pragma unroll 4
    for (int i = 0; i < 256; i++) {
        float v = h[(size_t)(r0 + i) * HDIM + c];
        cs += v;
        sq += v * v;
        if (r0 + i > 0) df += fabsf(v - prev);
        prev = v;
    }
    atomicAdd(&g_mu[c], (double)cs);

    #pragma unroll
    for (int off = 16; off > 0; off >>= 1) {
        sq += __shfl_down_sync(0xFFFFFFFFu, sq, off);
        df += __shfl_down_sync(0xFFFFFFFFu, df, off);
    }
    __shared__ float wsq[8], wdf[8];
    int tx = c & 31, ty = c >> 5;
    if (tx == 0) { wsq[ty] = sq; wdf[ty] = df; }
    __syncthreads();
    if (c == 0) {
        float s1 = 0.f, s2 = 0.f;
        #pragma unroll
        for (int w = 0; w < 8; w++) { s1 += wsq[w]; s2 += wdf[w]; }
        atomicAdd(&g_S, (double)s1);
        atomicAdd(&g_diff, (double)s2);
    }
}

__global__ void finalize_kernel(float* __restrict__ out, long long base)
{
    __shared__ double red[HDIM];
    int t = threadIdx.x;
    red[t] = fabs(g_mu[t]);
    __syncthreads();
    for (int s = 128; s > 0; s >>= 1) {
        if (t < s) red[t] += red[t + s];
        __syncthreads();
    }
    if (t == 0) {
        const double Nn = (double)NROWS;
        out[base + 0] = (float)(sqrt(g_part0) / (Nn - 1.0));
        out[base + 1] = (float)(red[0] / Nn / (double)HDIM);
        out[base + 2] = (float)fabs(g_S / Nn / (double)HDIM - 1.0);
        out[base + 3] = (float)(g_diff / (Nn - 1.0) / (double)HDIM);
    }
}

extern "C" void kernel_launch(void* const* d_in, const int* in_sizes, int n_in,
                              void* d_out, int out_size)
{
    const float* input = (const float*)d_in[0];
    const float* h     = (const float*)d_in[1];
    const float* W1    = (const float*)d_in[2];
    const float* b1    = (const float*)d_in[3];
    const float* W12   = (const float*)d_in[4];
    const float* b12   = (const float*)d_in[5];
    const float* W13   = (const float*)d_in[6];
    const float* b13   = (const float*)d_in[7];
    const float* W2    = (const float*)d_in[8];
    const float* b2    = (const float*)d_in[9];
    float* out = (float*)d_out;

    cudaFuncSetAttribute(mlp_kernel, cudaFuncAttributeMaxDynamicSharedMemorySize, SMEM_BYTES);

    zero_kernel<<<1, 256>>>();
    hred_kernel<<<NROWS / 256, HDIM>>>(h);
    dummy_kernel<<<1, 32>>>();
    mlp_kernel<<<NROWS / ROWS, TH, SMEM_BYTES>>>(input, h, W1, b1, W12, b12,
                                                 W13, b13, W2, b2, out);
    finalize_kernel<<<1, HDIM>>>(out, (long long)out_size - 4);
}

// round 13
// speedup vs baseline: 6.0269x; 1.5272x over previous
#include <cuda_runtime.h>
#include <cuda_bf16.h>
#include <math.h>

// Problem constants
#define NROWS 65536
#define PDIM  512
#define HDIM  256
#define DIN   768
#define D1    200
#define D2    100
#define D3    100
#define DOUT  512

#define ROWS  64      // rows per block
#define TH    512     // threads per block (16 warps: 4 row-groups x 4 n-quarters)

// ---- SMEM layout in u32 words.  All matrix data = packed bf16x2 hi/lo planes.
// Pitches mod 32 in {4,12,28} -> conflict-free LDS.32 fragment loads.
// Lifetimes: layer-1 double buffers (0..38016) die before h2/h3/W-staging live.
#define SM_H2    0            // h2: 2 planes x 64x60
#define SM_H3    7680         // h3: 2 planes x 64x60
#define SM_W     15360        // weight staging area (26624 words)
#define SM_H1    41984        // h1: 2 planes x 64x108
#define SM_TOT   55808        // words
#define SMEM_BYTES (SM_TOT * 4)   // 223232 bytes

// layer-1 double buffers: [xHi 2304 | xLo 2304 | wHi 7200 | wLo 7200] = 19008 words
#define BUFSZ    19008
#define BXH      0
#define BXL      2304
#define BWH      4608
#define BWL      11808

// Pre-split weight planes in global (written once per launch by presplit_kernel)
__device__ unsigned gW1 [2][200*384];   // k words 0..383 (768 k), no pad
__device__ unsigned gW12[2][104*104];   // rows 100..103 zero, words 100..103 zero
__device__ unsigned gW13[2][104*56];    // rows 100..103 zero, words 50..55 zero
__device__ unsigned gW2 [2][512*56];    // words 50..55 zero

// Global accumulators
__device__ double g_mu[HDIM];
__device__ double g_S;
__device__ double g_diff;
__device__ double g_part0;

__global__ void zero_kernel() {
    int t = threadIdx.x;
    if (t < HDIM) g_mu[t] = 0.0;
    if (t == 0) { g_S = 0.0; g_diff = 0.0; g_part0 = 0.0; }
}

// ---------------- bf16 split helpers ----------------
__device__ __forceinline__ void split2(float a, float b, unsigned &hi, unsigned &lo) {
    __nv_bfloat16 ha = __float2bfloat16_rn(a);
    __nv_bfloat16 hb = __float2bfloat16_rn(b);
    float la = a - __bfloat162float(ha);
    float lb = b - __bfloat162float(hb);
    __nv_bfloat162 hp; hp.x = ha; hp.y = hb;
    __nv_bfloat162 lp; lp.x = __float2bfloat16_rn(la); lp.y = __float2bfloat16_rn(lb);
    hi = *reinterpret_cast<unsigned*>(&hp);
    lo = *reinterpret_cast<unsigned*>(&lp);
}
__device__ __forceinline__ void split4w(float4 v, uint2 &h2v, uint2 &l2v) {
    split2(v.x, v.y, h2v.x, l2v.x);
    split2(v.z, v.w, h2v.y, l2v.y);
}

// One-time weight pre-split: fp32 -> packed bf16x2 hi/lo planes with pad baked in.
__global__ void presplit_kernel(const float* __restrict__ W1,  const float* __restrict__ W12,
                                const float* __restrict__ W13, const float* __restrict__ W2)
{
    int i = blockIdx.x * 256 + threadIdx.x;
    if (i < 76800) {                                 // W1: [200][384]
        int c = i / 384, w = i % 384;
        split2(W1[c*DIN + 2*w], W1[c*DIN + 2*w + 1], gW1[0][i], gW1[1][i]);
    } else if (i < 87616) {                          // W12: [104][104]
        int j = i - 76800; int c = j / 104, w = j % 104;
        float a = 0.f, b = 0.f;
        if (c < D2 && w < 100) { a = W12[c*D1 + 2*w]; b = W12[c*D1 + 2*w + 1]; }
        split2(a, b, gW12[0][j], gW12[1][j]);
    } else if (i < 93440) {                          // W13: [104][56]
        int j = i - 87616; int c = j / 56, w = j % 56;
        float a = 0.f, b = 0.f;
        if (c < D3 && w < 50) { a = W13[c*D2 + 2*w]; b = W13[c*D2 + 2*w + 1]; }
        split2(a, b, gW13[0][j], gW13[1][j]);
    } else if (i < 122112) {                         // W2: [512][56]
        int j = i - 93440; int c = j / 56, w = j % 56;
        float a = 0.f, b = 0.f;
        if (w < 50) { a = W2[c*D3 + 2*w]; b = W2[c*D3 + 2*w + 1]; }
        split2(a, b, gW2[0][j], gW2[1][j]);
    }
}

// ---------------- cp.async helpers ----------------
__device__ __forceinline__ void cp16(unsigned* smem_dst, const unsigned* gsrc) {
    unsigned saddr = (unsigned)__cvta_generic_to_shared(smem_dst);
    asm volatile("cp.async.ca.shared.global [%0], [%1], 16;" :: "r"(saddr), "l"(gsrc));
}
#define CP_COMMIT() asm volatile("cp.async.commit_group;")
#define CP_WAIT0()  asm volatile("cp.async.wait_group 0;" ::: "memory")

// flat plane copy via cp.async: rows x (qwords*4) words, dst pitch / src pitch
__device__ __forceinline__ void stage_flat(unsigned* dHi, unsigned* dLo,
                                           const unsigned* sHi, const unsigned* sLo,
                                           int rows, int qwords, int dpitch, int spitch,
                                           int tid)
{
    for (int i = tid; i < rows * qwords; i += TH) {
        int c = i / qwords, q = i % qwords;
        cp16(&dHi[c*dpitch + q*4], &sHi[c*spitch + q*4]);
        cp16(&dLo[c*dpitch + q*4], &sLo[c*spitch + q*4]);
    }
}

__device__ __forceinline__ void mma16(float* c,
                                      unsigned a0, unsigned a1, unsigned a2, unsigned a3,
                                      unsigned b0, unsigned b1) {
    asm volatile(
        "mma.sync.aligned.m16n8k16.row.col.f32.bf16.bf16.f32 "
        "{%0,%1,%2,%3}, {%4,%5,%6,%7}, {%8,%9}, {%0,%1,%2,%3};"
        : "+f"(c[0]), "+f"(c[1]), "+f"(c[2]), "+f"(c[3])
        : "r"(a0), "r"(a1), "r"(a2), "r"(a3), "r"(b0), "r"(b1));
}

// Warp GEMM, pre-split planes: inner work = LDS.32 + MMA only (3-term split).
template<int NT, int LDA, int LDB>
__device__ __forceinline__ void gemm_bf(float (*acc)[4],
                                        const unsigned* __restrict__ Ah,
                                        const unsigned* __restrict__ Al,
                                        const unsigned* __restrict__ Bh,
                                        const unsigned* __restrict__ Bl,
                                        int ksteps, int g, int tg)
{
    for (int ks = 0; ks < ksteps; ks++) {
        const int w0 = ks * 8;
        const int oA0 =  g      * LDA + w0 + tg;
        const int oA1 = (g + 8) * LDA + w0 + tg;
        unsigned ah0 = Ah[oA0], ah1 = Ah[oA1], ah2 = Ah[oA0 + 4], ah3 = Ah[oA1 + 4];
        unsigned al0 = Al[oA0], al1 = Al[oA1], al2 = Al[oA0 + 4], al3 = Al[oA1 + 4];
        #pragma unroll
        for (int t = 0; t < NT; t++) {
            const int bo = (t * 8 + g) * LDB + w0 + tg;
            unsigned bh0 = Bh[bo], bh1 = Bh[bo + 4];
            unsigned bl0 = Bl[bo], bl1 = Bl[bo + 4];
            mma16(acc[t], ah0, ah1, ah2, ah3, bh0, bh1);
            mma16(acc[t], ah0, ah1, ah2, ah3, bl0, bl1);
            mma16(acc[t], al0, al1, al2, al3, bh0, bh1);
        }
    }
}

template<int NT>
__device__ __forceinline__ void init_bias(float (*acc)[4], const float* __restrict__ bias,
                                          int n0, int tg, int nvalid)
{
    #pragma unroll
    for (int t = 0; t < NT; t++) {
        int c = n0 + t * 8 + tg * 2;
        float2 bv = make_float2(0.f, 0.f);
        if (c < nvalid) bv = *(const float2*)&bias[c];
        acc[t][0] = bv.x; acc[t][2] = bv.x;
        acc[t][1] = bv.y; acc[t][3] = bv.y;
    }
}

// relu + bf16 split + pack: cols (c, c+1) become next layer's k-pair word c/2.
template<int NT>
__device__ __forceinline__ void store_relu_bf(float (*acc)[4],
                                              unsigned* __restrict__ Hh,
                                              unsigned* __restrict__ Hl,
                                              int ldw, int m0, int n0,
                                              int g, int tg, int nvalid)
{
    #pragma unroll
    for (int t = 0; t < NT; t++) {
        int c = n0 + t * 8 + tg * 2;
        if (c < nvalid) {
            unsigned h0, l0, h1, l1;
            split2(fmaxf(acc[t][0], 0.f), fmaxf(acc[t][1], 0.f), h0, l0);
            split2(fmaxf(acc[t][2], 0.f), fmaxf(acc[t][3], 0.f), h1, l1);
            int o0 = (m0 + g) * ldw + (c >> 1);
            int o1 = (m0 + g + 8) * ldw + (c >> 1);
            Hh[o0] = h0; Hl[o0] = l0;
            Hh[o1] = h1; Hl[o1] = l1;
        }
    }
}

// x chunk global load (chunk cc covers k [cc*64, cc*64+64))
__device__ __forceinline__ float4 ldx(const float* __restrict__ input,
                                      const float* __restrict__ h,
                                      int row0, int cc, int i)
{
    int r = i >> 4, q = i & 15;
    int k0 = cc * 64;
    const float* src; int ss;
    if (k0 < PDIM) { src = input + (size_t)row0 * PDIM + k0; ss = PDIM; }
    else           { src = h     + (size_t)row0 * HDIM + (k0 - PDIM); ss = HDIM; }
    return *(const float4*)(src + (size_t)r * ss + q * 4);
}
__device__ __forceinline__ void stx(unsigned* xHi, unsigned* xLo, int i, float4 v) {
    int r = i >> 4, q = i & 15;
    uint2 hw, lw; split4w(v, hw, lw);
    *(uint2*)&xHi[r * 36 + q * 2] = hw;
    *(uint2*)&xLo[r * 36 + q * 2] = lw;
}

__global__ __launch_bounds__(TH, 1)
void mlp_kernel(const float* __restrict__ input,
                const float* __restrict__ h,
                const float* __restrict__ b1,  const float* __restrict__ b12,
                const float* __restrict__ b13, const float* __restrict__ b2,
                float* __restrict__ out)
{
    extern __shared__ unsigned smem[];
    unsigned* h2Hi = smem + SM_H2;  unsigned* h2Lo = h2Hi + 3840;   // 64x60
    unsigned* h3Hi = smem + SM_H3;  unsigned* h3Lo = h3Hi + 3840;   // 64x60
    unsigned* h1Hi = smem + SM_H1;  unsigned* h1Lo = h1Hi + 6912;   // 64x108

    const int tid  = threadIdx.x;
    const int lane = tid & 31;
    const int wid  = tid >> 5;     // 0..15
    const int g    = lane >> 2;
    const int tg   = lane & 3;
    const int rowg = wid >> 2;     // 0..3
    const int nq   = wid & 3;      // n-quarter
    const int m0   = rowg * 16;
    const int row0 = blockIdx.x * ROWS;

    float acc[7][4];

    const int L1_N0[4]  = {0, 56, 104, 152};   // 25 tiles -> {7,6,6,6}
    const int L23_N0[4] = {0, 32, 56, 80};     // 13 tiles -> {4,3,3,3}

    // ===================== Layer 1: [64x768] @ W1^T -> relu [64x200] =====================
    // double-buffered: cp.async weights + prefetched x, one barrier per chunk
    if (nq == 0) init_bias<7>(acc, b1, 0, tg, D1);
    else         init_bias<6>(acc, b1, L1_N0[nq], tg, D1);

    // prologue: stage chunk 0 into buf0
    {
        unsigned* buf = smem;   // buf0
        for (int i = tid; i < 200 * 8; i += TH) {
            int c = i >> 3, q = i & 7;
            cp16(&buf[BWH + c*36 + q*4], &gW1[0][c*384 + q*4]);
            cp16(&buf[BWL + c*36 + q*4], &gW1[1][c*384 + q*4]);
        }
        CP_COMMIT();
        float4 xv0 = ldx(input, h, row0, 0, tid);
        float4 xv1 = ldx(input, h, row0, 0, tid + TH);
        stx(buf + BXH, buf + BXL, tid,      xv0);
        stx(buf + BXH, buf + BXL, tid + TH, xv1);
        CP_WAIT0();
    }
    __syncthreads();

    #pragma unroll 1
    for (int ch = 0; ch < 12; ch++) {
        unsigned* cur = smem + (ch & 1) * BUFSZ;
        unsigned* nxt = smem + ((ch + 1) & 1) * BUFSZ;
        float4 xv0, xv1;
        if (ch < 11) {
            // issue next weight chunk + load next x chunk (overlaps compute below)
            for (int i = tid; i < 200 * 8; i += TH) {
                int c = i >> 3, q = i & 7;
                cp16(&nxt[BWH + c*36 + q*4], &gW1[0][c*384 + (ch+1)*32 + q*4]);
                cp16(&nxt[BWL + c*36 + q*4], &gW1[1][c*384 + (ch+1)*32 + q*4]);
            }
            CP_COMMIT();
            xv0 = ldx(input, h, row0, ch + 1, tid);
            xv1 = ldx(input, h, row0, ch + 1, tid + TH);
        }
        // compute chunk ch
        {
            const unsigned* Ah = cur + BXH + m0 * 36;
            const unsigned* Al = cur + BXL + m0 * 36;
            int o = L1_N0[nq] * 36;
            if (nq == 0) gemm_bf<7, 36, 36>(acc, Ah, Al, cur + BWH, cur + BWL, 4, g, tg);
            else         gemm_bf<6, 36, 36>(acc, Ah, Al, cur + BWH + o, cur + BWL + o, 4, g, tg);
        }
        if (ch < 11) {
            stx(nxt + BXH, nxt + BXL, tid,      xv0);
            stx(nxt + BXH, nxt + BXL, tid + TH, xv1);
            CP_WAIT0();
        }
        __syncthreads();
    }

    // h1 store (region untouched by buffers) + pads + stage W12; single barrier
    if (nq == 0) store_relu_bf<7>(acc, h1Hi, h1Lo, 108, m0, 0, g, tg, D1);
    else         store_relu_bf<6>(acc, h1Hi, h1Lo, 108, m0, L1_N0[nq], g, tg, D1);
    {
        unsigned* wHi = smem + SM_W;          // W12 plane pitch 108 (11232 words)
        unsigned* wLo = wHi + 11232;
        stage_flat(wHi, wLo, gW12[0], gW12[1], 104, 26, 108, 104, tid);
        CP_COMMIT();
        // zero pads: h1 words 100..103, h2/h3 words 50..55 (buffer space now dead)
        for (int i = tid; i < 64 * 4; i += TH) {
            int r = i >> 2, w = 100 + (i & 3);
            h1Hi[r * 108 + w] = 0; h1Lo[r * 108 + w] = 0;
        }
        for (int i = tid; i < 64 * 6; i += TH) {
            int r = i / 6, w = 50 + (i % 6);
            h2Hi[r * 60 + w] = 0; h2Lo[r * 60 + w] = 0;
            h3Hi[r * 60 + w] = 0; h3Lo[r * 60 + w] = 0;
        }
        CP_WAIT0();
    }
    __syncthreads();

    // ===================== Layer 2: [64x200] @ W12^T -> relu [64x100] =====================
    {
        unsigned* wHi = smem + SM_W; unsigned* wLo = wHi + 11232;
        const unsigned* Ah = h1Hi + m0 * 108;
        const unsigned* Al = h1Lo + m0 * 108;
        int o = L23_N0[nq] * 108;
        if (nq == 0) {
            init_bias<4>(acc, b12, 0, tg, D2);
            gemm_bf<4, 108, 108>(acc, Ah, Al, wHi + o, wLo + o, 13, g, tg);
            store_relu_bf<4>(acc, h2Hi, h2Lo, 60, m0, 0, g, tg, D2);
        } else {
            init_bias<3>(acc, b12, L23_N0[nq], tg, D2);
            gemm_bf<3, 108, 108>(acc, Ah, Al, wHi + o, wLo + o, 13, g, tg);
            store_relu_bf<3>(acc, h2Hi, h2Lo, 60, m0, L23_N0[nq], g, tg, D2);
        }
    }
    __syncthreads();

    // stage W13 (pitch 60, 6240 words/plane)
    {
        unsigned* wHi = smem + SM_W; unsigned* wLo = wHi + 6240;
        stage_flat(wHi, wLo, gW13[0], gW13[1], 104, 14, 60, 56, tid);
        CP_COMMIT(); CP_WAIT0();
    }
    __syncthreads();

    // ===================== Layer 3: [64x100] @ W13^T -> relu [64x100] =====================
    {
        unsigned* wHi = smem + SM_W; unsigned* wLo = wHi + 6240;
        const unsigned* Ah = h2Hi + m0 * 60;
        const unsigned* Al = h2Lo + m0 * 60;
        int o = L23_N0[nq] * 60;
        if (nq == 0) {
            init_bias<4>(acc, b13, 0, tg, D3);
            gemm_bf<4, 60, 60>(acc, Ah, Al, wHi + o, wLo + o, 7, g, tg);
            store_relu_bf<4>(acc, h3Hi, h3Lo, 60, m0, 0, g, tg, D3);
        } else {
            init_bias<3>(acc, b13, L23_N0[nq], tg, D3);
            gemm_bf<3, 60, 60>(acc, Ah, Al, wHi + o, wLo + o, 7, g, tg);
            store_relu_bf<3>(acc, h3Hi, h3Lo, 60, m0, L23_N0[nq], g, tg, D3);
        }
    }
    __syncthreads();

    // ===================== Layer 4: 8 chunks of 64 cols, double-buffered ==================
    // W2 chunk buffers: A @ SM_W, B @ SM_W+7680 (each 2 planes x 64x60)
    {
        unsigned* bufA = smem + SM_W;
        stage_flat(bufA, bufA + 3840, gW2[0], gW2[1], 64, 14, 60, 56, tid);
        CP_COMMIT(); CP_WAIT0();
    }
    __syncthreads();

    float dd = 0.f;
    #pragma unroll 1
    for (int c4 = 0; c4 < 8; c4++) {
        unsigned* cur = smem + SM_W + (c4 & 1) * 7680;
        unsigned* nxt = smem + SM_W + ((c4 + 1) & 1) * 7680;
        if (c4 < 7) {
            stage_flat(nxt, nxt + 3840, gW2[0] + (c4 + 1) * 64 * 56,
                       gW2[1] + (c4 + 1) * 64 * 56, 64, 14, 60, 56, tid);
            CP_COMMIT();
        }
        init_bias<2>(acc, b2, c4 * 64 + nq * 16, tg, DOUT);
        {
            const unsigned* Ah = h3Hi + m0 * 60;
            const unsigned* Al = h3Lo + m0 * 60;
            int o = nq * 16 * 60;
            gemm_bf<2, 60, 60>(acc, Ah, Al, cur + o, cur + 3840 + o, 7, g, tg);
        }
        #pragma unroll
        for (int t = 0; t < 2; t++) {
            int c  = c4 * 64 + nq * 16 + t * 8 + tg * 2;
            int r1 = row0 + m0 + g;
            int r2 = r1 + 8;
            float2 v0 = make_float2(acc[t][0], acc[t][1]);
            float2 v1 = make_float2(acc[t][2], acc[t][3]);
            *(float2*)&out[(size_t)r1 * PDIM + c] = v0;
            *(float2*)&out[(size_t)r2 * PDIM + c] = v1;
            if (r1 < NROWS - 1) {
                float2 nx = *(const float2*)&input[(size_t)(r1 + 1) * PDIM + c];
                float d0 = v0.x - nx.x, d1 = v0.y - nx.y;
                dd += d0 * d0 + d1 * d1;
            }
            if (r2 < NROWS - 1) {
                float2 nx = *(const float2*)&input[(size_t)(r2 + 1) * PDIM + c];
                float d0 = v1.x - nx.x, d1 = v1.y - nx.y;
                dd += d0 * d0 + d1 * d1;
            }
        }
        if (c4 < 7) CP_WAIT0();
        __syncthreads();
    }

    // reduce dd -> g_part0
    #pragma unroll
    for (int off = 16; off > 0; off >>= 1)
        dd += __shfl_down_sync(0xFFFFFFFFu, dd, off);
    __shared__ float wdd[16];
    if (lane == 0) wdd[wid] = dd;
    __syncthreads();
    if (tid == 0) {
        float s = 0.f;
        #pragma unroll
        for (int w = 0; w < 16; w++) s += wdd[w];
        atomicAdd(&g_part0, (double)s);
    }
}

// h statistics: column sums (mu), sum of squares (S), total variation (diff)
__global__ __launch_bounds__(HDIM)
void hred_kernel(const float* __restrict__ h)
{
    const int c  = threadIdx.x;
    const int r0 = blockIdx.x * 256;
    float prev = (r0 > 0) ? h[(size_t)(r0 - 1) * HDIM + c] : 0.f;
    float cs = 0.f, sq = 0.f, df = 0.f;
    #pragma unroll 4
    for (int i = 0; i < 256; i++) {
        float v = h[(size_t)(r0 + i) * HDIM + c];
        cs += v;
        sq += v * v;
        if (r0 + i > 0) df += fabsf(v - prev);
        prev = v;
    }
    atomicAdd(&g_mu[c], (double)cs);

    #pragma unroll
    for (int off = 16; off > 0; off >>= 1) {
        sq += __shfl_down_sync(0xFFFFFFFFu, sq, off);
        df += __shfl_down_sync(0xFFFFFFFFu, df, off);
    }
    __shared__ float wsq[8], wdf[8];
    int tx = c & 31, ty = c >> 5;
    if (tx == 0) { wsq[ty] = sq; wdf[ty] = df; }
    __syncthreads();
    if (c == 0) {
        float s1 = 0.f, s2 = 0.f;
        #pragma unroll
        for (int w = 0; w < 8; w++) { s1 += wsq[w]; s2 += wdf[w]; }
        atomicAdd(&g_S, (double)s1);
        atomicAdd(&g_diff, (double)s2);
    }
}

__global__ void finalize_kernel(float* __restrict__ out, long long base)
{
    __shared__ double red[HDIM];
    int t = threadIdx.x;
    red[t] = fabs(g_mu[t]);
    __syncthreads();
    for (int s = 128; s > 0; s >>= 1) {
        if (t < s) red[t] += red[t + s];
        __syncthreads();
    }
    if (t == 0) {
        const double Nn = (double)NROWS;
        out[base + 0] = (float)(sqrt(g_part0) / (Nn - 1.0));
        out[base + 1] = (float)(red[0] / Nn / (double)HDIM);
        out[base + 2] = (float)fabs(g_S / Nn / (double)HDIM - 1.0);
        out[base + 3] = (float)(g_diff / (Nn - 1.0) / (double)HDIM);
    }
}

extern "C" void kernel_launch(void* const* d_in, const int* in_sizes, int n_in,
                              void* d_out, int out_size)
{
    const float* input = (const float*)d_in[0];
    const float* h     = (const float*)d_in[1];
    const float* W1    = (const float*)d_in[2];
    const float* b1    = (const float*)d_in[3];
    const float* W12   = (const float*)d_in[4];
    const float* b12   = (const float*)d_in[5];
    const float* W13   = (const float*)d_in[6];
    const float* b13   = (const float*)d_in[7];
    const float* W2    = (const float*)d_in[8];
    const float* b2    = (const float*)d_in[9];
    float* out = (float*)d_out;

    cudaFuncSetAttribute(mlp_kernel, cudaFuncAttributeMaxDynamicSharedMemorySize, SMEM_BYTES);

    zero_kernel<<<1, 256>>>();
    presplit_kernel<<<478, 256>>>(W1, W12, W13, W2);
    hred_kernel<<<NROWS / 256, HDIM>>>(h);
    mlp_kernel<<<NROWS / ROWS, TH, SMEM_BYTES>>>(input, h, b1, b12, b13, b2, out);
    finalize_kernel<<<1, HDIM>>>(out, (long long)out_size - 4);
}